// round 1
// baseline (speedup 1.0000x reference)
#include <cuda_runtime.h>

#define NB 128
#define NI 512
#define NH 256
#define NOF 512   // O*F = 32*16

// Scratch (allocation-free rule: __device__ globals). Zero-initialized at load;
// every squash kernel re-zeros g_vacc after reading so state is replay-invariant.
__device__ float g_U[(size_t)NB * NI * NOF];   // u: [B*I, O*F] row-major, 134 MB
__device__ float g_vacc[NB * NOF];
__device__ float g_vsq[NB * NOF];

// ---------- packed f32x2 helpers (FFMA2: 2x fp32 FMA throughput on sm_103a) ----------
__device__ __forceinline__ unsigned long long pack_dup(float a) {
    unsigned long long r;
    asm("mov.b64 %0, {%1, %1};" : "=l"(r) : "f"(a));
    return r;
}
__device__ __forceinline__ void ffma2(unsigned long long& d, unsigned long long a,
                                      unsigned long long b) {
    asm("fma.rn.f32x2 %0, %1, %2, %0;" : "+l"(d) : "l"(a), "l"(b));
}
__device__ __forceinline__ float2 unpack2(unsigned long long v) {
    float2 f;
    asm("mov.b64 {%0, %1}, %2;" : "=f"(f.x), "=f"(f.y) : "l"(v));
    return f;
}

// ---------- SGEMM: g_U[M, 512] = x[M, 256] * W[256, 512], M = 65536 ----------
// 128x128 block tile, BK=8, 256 threads, 8x8 per thread, f32x2 packed accumulators.
__global__ __launch_bounds__(256, 2) void sgemm_kernel(const float* __restrict__ A,
                                                       const float* __restrict__ B) {
    const int K = NH, N = NOF;
    __shared__ float As[8][128];
    __shared__ float Bs[8][128];
    int tid = threadIdx.x;
    int tr = tid >> 4;          // 0..15 (thread row)
    int tc = tid & 15;          // 0..15 (thread col)
    int rowBase = blockIdx.y << 7;
    int colBase = blockIdx.x << 7;

    const float* Ag = A + (size_t)(rowBase + (tid >> 1)) * K + ((tid & 1) << 2);
    const float* Bg = B + (size_t)(tid >> 5) * N + colBase + ((tid & 31) << 2);

    unsigned long long acc[8][4];
#pragma unroll
    for (int i = 0; i < 8; i++)
#pragma unroll
        for (int j = 0; j < 4; j++) acc[i][j] = 0ull;

    for (int kt = 0; kt < K; kt += 8) {
        float4 a = *(const float4*)(Ag + kt);
        int ac = (tid & 1) << 2;
        int ar = tid >> 1;
        As[ac + 0][ar] = a.x;
        As[ac + 1][ar] = a.y;
        As[ac + 2][ar] = a.z;
        As[ac + 3][ar] = a.w;
        *(float4*)&Bs[tid >> 5][(tid & 31) << 2] = *(const float4*)(Bg + (size_t)kt * N);
        __syncthreads();
#pragma unroll
        for (int k = 0; k < 8; k++) {
            const ulonglong2* bp = (const ulonglong2*)&Bs[k][tc << 3];
            ulonglong2 b01 = bp[0], b23 = bp[1];
            unsigned long long bn0 = b01.x, bn1 = b01.y, bn2 = b23.x, bn3 = b23.y;
            const float* ap = &As[k][tr << 3];
#pragma unroll
            for (int i = 0; i < 8; i++) {
                unsigned long long m2 = pack_dup(ap[i]);
                ffma2(acc[i][0], m2, bn0);
                ffma2(acc[i][1], m2, bn1);
                ffma2(acc[i][2], m2, bn2);
                ffma2(acc[i][3], m2, bn3);
            }
        }
        __syncthreads();
    }

    float* Cg = g_U + (size_t)(rowBase + (tr << 3)) * N + colBase + (tc << 3);
#pragma unroll
    for (int i = 0; i < 8; i++) {
        float2 c0 = unpack2(acc[i][0]);
        float2 c1 = unpack2(acc[i][1]);
        float2 c2 = unpack2(acc[i][2]);
        float2 c3 = unpack2(acc[i][3]);
        *(float4*)(Cg + (size_t)i * N)     = make_float4(c0.x, c0.y, c1.x, c1.y);
        *(float4*)(Cg + (size_t)i * N + 4) = make_float4(c2.x, c2.y, c3.x, c3.y);
    }
}

// ---------- Routing pass: one streaming pass over u ----------
// For each (b, i): warp lane o holds u[b,i,o,0..15] in 16 regs.
//   first=1:  c = 1/32 (softmax of zeros)
//   first=0:  bb = v_sq . u  (dot over f), softmax over 32 lanes (=O), c = softmax
// Accumulate v_new[o,f] += c * u[o,f]; reduce block-locally, then global atomics.
// grid = NB*8 blocks (8 i-chunks of 64 per batch), 256 threads (8 warps x 8 i each).
__global__ __launch_bounds__(256) void route_pass_kernel(int first) {
    __shared__ float vs[NOF];
    int b = blockIdx.x >> 3;
    int chunk = blockIdx.x & 7;
    int warp = threadIdx.x >> 5;
    int lane = threadIdx.x & 31;

    vs[threadIdx.x] = 0.f;
    vs[threadIdx.x + 256] = 0.f;

    float vr[16];
    if (!first) {
        const float4* vp = (const float4*)(g_vsq + b * NOF + (lane << 4));
        float4 v0 = vp[0], v1 = vp[1], v2 = vp[2], v3 = vp[3];
        vr[0] = v0.x; vr[1] = v0.y; vr[2] = v0.z; vr[3] = v0.w;
        vr[4] = v1.x; vr[5] = v1.y; vr[6] = v1.z; vr[7] = v1.w;
        vr[8] = v2.x; vr[9] = v2.y; vr[10] = v2.z; vr[11] = v2.w;
        vr[12] = v3.x; vr[13] = v3.y; vr[14] = v3.z; vr[15] = v3.w;
    }
    __syncthreads();

    float acc[16];
#pragma unroll
    for (int f = 0; f < 16; f++) acc[f] = 0.f;

    const float* Ub = g_U + (size_t)b * NI * NOF;
#pragma unroll
    for (int j = 0; j < 8; j++) {
        int i = (chunk << 6) + (warp << 3) + j;
        const float4* up = (const float4*)(Ub + (size_t)i * NOF + (lane << 4));
        float4 u0 = up[0], u1 = up[1], u2 = up[2], u3 = up[3];
        float c;
        if (first) {
            c = 1.0f / 32.0f;
        } else {
            float bb = u0.x * vr[0] + u0.y * vr[1] + u0.z * vr[2] + u0.w * vr[3]
                     + u1.x * vr[4] + u1.y * vr[5] + u1.z * vr[6] + u1.w * vr[7]
                     + u2.x * vr[8] + u2.y * vr[9] + u2.z * vr[10] + u2.w * vr[11]
                     + u3.x * vr[12] + u3.y * vr[13] + u3.z * vr[14] + u3.w * vr[15];
            float mx = bb;
#pragma unroll
            for (int m = 16; m > 0; m >>= 1)
                mx = fmaxf(mx, __shfl_xor_sync(0xffffffffu, mx, m));
            float e = __expf(bb - mx);
            float s = e;
#pragma unroll
            for (int m = 16; m > 0; m >>= 1)
                s += __shfl_xor_sync(0xffffffffu, s, m);
            c = e / s;
        }
        acc[0] += c * u0.x;  acc[1] += c * u0.y;  acc[2] += c * u0.z;  acc[3] += c * u0.w;
        acc[4] += c * u1.x;  acc[5] += c * u1.y;  acc[6] += c * u1.z;  acc[7] += c * u1.w;
        acc[8] += c * u2.x;  acc[9] += c * u2.y;  acc[10] += c * u2.z; acc[11] += c * u2.w;
        acc[12] += c * u3.x; acc[13] += c * u3.y; acc[14] += c * u3.z; acc[15] += c * u3.w;
    }

#pragma unroll
    for (int f = 0; f < 16; f++) atomicAdd(&vs[(lane << 4) + f], acc[f]);
    __syncthreads();
    atomicAdd(&g_vacc[b * NOF + threadIdx.x], vs[threadIdx.x]);
    atomicAdd(&g_vacc[b * NOF + 256 + threadIdx.x], vs[threadIdx.x + 256]);
}

// ---------- Squash: v = v * ||v|| / (1 + ||v||^2), per (b,o) over f ----------
// Also re-zeros g_vacc (ready for next pass / next graph replay).
// grid = NB blocks, 512 threads: tid = o*16 + f.
__global__ __launch_bounds__(512) void squash_kernel(float* __restrict__ outp) {
    int idx = blockIdx.x * NOF + threadIdx.x;
    float val = g_vacc[idx];
    g_vacc[idx] = 0.f;
    float n2 = val * val;
#pragma unroll
    for (int m = 8; m > 0; m >>= 1)
        n2 += __shfl_xor_sync(0xffffffffu, n2, m);   // sum over the 16 f-lanes
    float scale = sqrtf(n2) / (1.0f + n2);
    float r = val * scale;
    if (outp) outp[idx] = r;
    else g_vsq[idx] = r;
}

extern "C" void kernel_launch(void* const* d_in, const int* in_sizes, int n_in,
                              void* d_out, int out_size) {
    const float* x = (const float*)d_in[0];   // [128, 512, 256]
    const float* W = (const float*)d_in[1];   // [1, 256, 512]
    float* out = (float*)d_out;               // [128, 32, 16]

    sgemm_kernel<<<dim3(NOF / 128, (NB * NI) / 128), 256>>>(x, W);

    route_pass_kernel<<<NB * 8, 256>>>(1);    // iter 1: c uniform (b=0)
    squash_kernel<<<NB, 512>>>(nullptr);      // v1

    route_pass_kernel<<<NB * 8, 256>>>(0);    // iter 2
    squash_kernel<<<NB, 512>>>(nullptr);      // v2

    route_pass_kernel<<<NB * 8, 256>>>(0);    // iter 3
    squash_kernel<<<NB, 512>>>(out);          // v3 -> output
}

// round 3
// speedup vs baseline: 2.9313x; 2.9313x over previous
#include <cuda_runtime.h>
#include <cstdint>

#define NB 128
#define NI 512
#define NH 256
#define NOF 512   // O*F = 32*16

// Arch-feature gate: tcgen05 only exists in the sm_103a (arch-specific) pass.
// The plain compute_103/sm_103 pass compiles the FFMA2 fallback instead.
#if defined(__CUDA_ARCH__) && \
    (defined(__CUDA_ARCH_FEAT_SM103_ALL) || defined(__CUDA_ARCH_FEAT_SM101_ALL) || \
     (defined(__CUDA_ARCH_SPECIFIC__) && (__CUDA_ARCH_SPECIFIC__ == 1030)))
#define TC_PATH 1
#else
#define TC_PATH 0
#endif

// ---------------- device scratch (allocation-free rule) ----------------
__device__ float g_U[(size_t)NB * NI * NOF];   // u: [B*I, 512] row-major
__device__ float g_Wt[NOF * NH];               // W^T [512, 256], tf32-rounded
__device__ float g_vacc[NB * NOF];
__device__ float g_vsq[NB * NOF];

// ---------------- generic helpers ----------------
__device__ __forceinline__ uint32_t smem_u32(const void* p) {
    uint32_t a;
    asm("{ .reg .u64 t; cvta.to.shared.u64 t, %1; cvt.u32.u64 %0, t; }" : "=r"(a) : "l"(p));
    return a;
}
__device__ __forceinline__ float to_tf32(float x) {
    float r;
    asm("cvt.rna.tf32.f32 %0, %1;" : "=f"(r) : "f"(x));
    return r;
}
__device__ __forceinline__ uint32_t sw128(uint32_t off) { return off ^ ((off >> 3) & 0x70); }

// packed f32x2 helpers (fallback GEMM)
__device__ __forceinline__ unsigned long long pack_dup(float a) {
    unsigned long long r;
    asm("mov.b64 %0, {%1, %1};" : "=l"(r) : "f"(a));
    return r;
}
__device__ __forceinline__ void ffma2(unsigned long long& d, unsigned long long a,
                                      unsigned long long b) {
    asm("fma.rn.f32x2 %0, %1, %2, %0;" : "+l"(d) : "l"(a), "l"(b));
}
__device__ __forceinline__ float2 unpack2(unsigned long long v) {
    float2 f;
    asm("mov.b64 {%0, %1}, %2;" : "=f"(f.x), "=f"(f.y) : "l"(v));
    return f;
}

// ---------------- W transpose + tf32 round: g_Wt[n][k] = tf32(W[k][n]) ----------------
__global__ __launch_bounds__(256) void wt_kernel(const float* __restrict__ W) {
    int idx = blockIdx.x * 256 + threadIdx.x;   // 512*256 = 131072
    int n = idx >> 8, k = idx & 255;
    g_Wt[idx] = to_tf32(W[(size_t)k * NOF + n]);
}

// ---------------- SMEM layout for the GEMM kernel ----------------
#define SM_TMEM 0
#define SM_MB0 8
#define SM_MB1 16
#define SM_COLSUM 512
#define SM_A0 1024
#define SM_A1 (SM_A0 + 16384)
#define SM_B0 (SM_A1 + 16384)
#define SM_B1 (SM_B0 + 32768)
#define GEMM_SMEM (SM_B1 + 32768 + 128)

#if TC_PATH
// ---------------- tcgen05-only PTX helpers ----------------
__device__ __forceinline__ uint32_t elect_one_pred() {
    uint32_t pred;
    asm volatile("{\n\t.reg .pred p;\n\telect.sync _|p, 0xFFFFFFFF;\n\t"
                 "selp.b32 %0, 1, 0, p;\n\t}" : "=r"(pred));
    return pred;
}
#define TCGEN05_ALLOC(sa, n) \
    asm volatile("tcgen05.alloc.cta_group::1.sync.aligned.shared::cta.b32 [%0], %1;" \
                 :: "r"((uint32_t)(sa)), "r"((uint32_t)(n)) : "memory")
#define TCGEN05_DEALLOC(t, n) \
    asm volatile("tcgen05.dealloc.cta_group::1.sync.aligned.b32 %0, %1;" :: "r"(t), "r"((uint32_t)(n)))
#define TCGEN05_RELINQ() \
    asm volatile("tcgen05.relinquish_alloc_permit.cta_group::1.sync.aligned;")
#define TCGEN05_COMMIT(mb) \
    asm volatile("tcgen05.commit.cta_group::1.mbarrier::arrive::one.shared::cluster.b64 [%0];" \
                 :: "r"((uint32_t)(mb)) : "memory")
#define TCGEN05_FENCE_AFTER() asm volatile("tcgen05.fence::after_thread_sync;" ::: "memory")
#define TCGEN05_WAIT_LD() asm volatile("tcgen05.wait::ld.sync.aligned;" ::: "memory")
#define FENCE_ASYNC_SHARED() asm volatile("fence.proxy.async.shared::cta;" ::: "memory")
#define MBAR_INIT(mb, c) \
    asm volatile("mbarrier.init.shared.b64 [%0], %1;" :: "r"((uint32_t)(mb)), "r"((uint32_t)(c)) : "memory")
#define MBAR_INVAL(mb) \
    asm volatile("mbarrier.inval.shared.b64 [%0];" :: "r"((uint32_t)(mb)) : "memory")

__device__ __forceinline__ void mbar_wait_parity(uint32_t mb, uint32_t parity) {
    asm volatile(
        "{\n\t.reg .pred P1;\n\t"
        "WAIT_LOOP_%=:\n\t"
        "mbarrier.try_wait.parity.acquire.cta.shared::cta.b64 P1, [%0], %1, 0x989680;\n\t"
        "@P1 bra.uni WAIT_DONE_%=;\n\t"
        "bra.uni WAIT_LOOP_%=;\n\t"
        "WAIT_DONE_%=:\n\t}"
        :: "r"(mb), "r"(parity) : "memory");
}

#define LD32X32_X32(r, ta) \
    asm volatile( \
        "tcgen05.ld.sync.aligned.32x32b.x32.b32 " \
        "{%0, %1, %2, %3, %4, %5, %6, %7, %8, %9, %10, %11, %12, %13, %14, %15, " \
        " %16, %17, %18, %19, %20, %21, %22, %23, %24, %25, %26, %27, %28, %29, %30, %31}, [%32];" \
        : "=r"((r)[0]),  "=r"((r)[1]),  "=r"((r)[2]),  "=r"((r)[3]), \
          "=r"((r)[4]),  "=r"((r)[5]),  "=r"((r)[6]),  "=r"((r)[7]), \
          "=r"((r)[8]),  "=r"((r)[9]),  "=r"((r)[10]), "=r"((r)[11]), \
          "=r"((r)[12]), "=r"((r)[13]), "=r"((r)[14]), "=r"((r)[15]), \
          "=r"((r)[16]), "=r"((r)[17]), "=r"((r)[18]), "=r"((r)[19]), \
          "=r"((r)[20]), "=r"((r)[21]), "=r"((r)[22]), "=r"((r)[23]), \
          "=r"((r)[24]), "=r"((r)[25]), "=r"((r)[26]), "=r"((r)[27]), \
          "=r"((r)[28]), "=r"((r)[29]), "=r"((r)[30]), "=r"((r)[31]) \
        : "r"(ta))

__device__ __forceinline__ void mma_tf32_ss(uint32_t d, uint64_t ad, uint64_t bd,
                                            uint32_t idesc, bool en) {
    uint32_t e = en ? 1u : 0u, z = 0u;
    asm volatile(
        "{\n\t.reg .pred p;\n\tsetp.ne.u32 p, %6, 0;\n\t"
        "tcgen05.mma.cta_group::1.kind::tf32 [%0], %1, %2, %3, {%4, %4, %4, %4}, p;\n\t}"
        :: "r"(d), "l"(ad), "l"(bd), "r"(idesc), "r"(z), "r"(z), "r"(e)
        : "memory");
}
__device__ __forceinline__ uint64_t make_desc_sw128(uint32_t base) {
    const uint64_t BASE =
        (uint64_t(2) << 61) | (uint64_t(1) << 46) | (uint64_t(64) << 32) | (uint64_t(1) << 16);
    return BASE | ((uint64_t)(base >> 4) & 0x3FFF);
}
// idesc (f16 family): dtype F32=1<<4, atype TF32=2<<7, btype TF32=2<<10,
// N=256 -> (256>>3)<<17, M=128 -> (128>>4)<<24
#define TF32_IDESC (0x10u | (2u << 7) | (2u << 10) | ((256u >> 3) << 17) | ((128u >> 4) << 24))
#endif  // TC_PATH

// ---------------- GEMM: U[65536, 512] = X[65536, 256] * W, fused iter-1 colsums ----------
// grid = (2, 512), 256 threads. Per CTA: 128 rows x 256 cols.
__global__ __launch_bounds__(256) void gemm_tc(const float* __restrict__ X,
                                               const float* __restrict__ W) {
    extern __shared__ char smem[];
    int tid = threadIdx.x;
    int rowBase = blockIdx.y << 7;
    int colBase = blockIdx.x << 8;
    int b = rowBase >> 9;                // batch index (512 rows per batch)

#if TC_PATH
    const uint32_t sb = smem_u32(smem);
    int wid = tid >> 5, lane = tid & 31;

    if (wid == 0) {
        TCGEN05_ALLOC(sb + SM_TMEM, 256);
        TCGEN05_RELINQ();
    }
    if (tid == 0) { MBAR_INIT(sb + SM_MB0, 1); MBAR_INIT(sb + SM_MB1, 1); }
    __syncthreads();
    uint32_t tmem;
    asm volatile("ld.shared.b32 %0, [%1];" : "=r"(tmem) : "r"(sb + SM_TMEM));

    int ph0 = 0, ph1 = 0;
    for (int ch = 0; ch < 8; ch++) {
        int buf = ch & 1;
        uint32_t Aoff = buf ? SM_A1 : SM_A0;
        uint32_t Boff = buf ? SM_B1 : SM_B0;
        if (ch >= 2) {
            if (buf == 0) { mbar_wait_parity(sb + SM_MB0, ph0 & 1); ph0++; }
            else          { mbar_wait_parity(sb + SM_MB1, ph1 & 1); ph1++; }
        }
        // A: 128 rows x 32 f32 (128B/row), RN-convert to tf32, SW128 swizzle
#pragma unroll
        for (int p = 0; p < 4; p++) {
            int unit = tid + (p << 8);
            int r = unit >> 3, j = unit & 7;
            float4 v = *(const float4*)(X + (size_t)(rowBase + r) * NH + ch * 32 + j * 4);
            v.x = to_tf32(v.x); v.y = to_tf32(v.y); v.z = to_tf32(v.z); v.w = to_tf32(v.w);
            *(float4*)(smem + Aoff + sw128(r * 128 + j * 16)) = v;
        }
        // B: 256 rows x 32 f32 (pre-converted tf32 W^T), SW128 swizzle
#pragma unroll
        for (int p = 0; p < 8; p++) {
            int unit = tid + (p << 8);
            int r = unit >> 3, j = unit & 7;
            float4 v = *(const float4*)(g_Wt + (size_t)(colBase + r) * NH + ch * 32 + j * 4);
            *(float4*)(smem + Boff + sw128(r * 128 + j * 16)) = v;
        }
        FENCE_ASYNC_SHARED();
        __syncthreads();
        if (wid == 0) {
            uint64_t ad = make_desc_sw128(sb + Aoff);
            uint64_t bd = make_desc_sw128(sb + Boff);
            if (elect_one_pred()) {
#pragma unroll
                for (int k = 0; k < 4; k++)
                    mma_tf32_ss(tmem, ad + k * 2, bd + k * 2, TF32_IDESC, (ch > 0) || (k > 0));
                TCGEN05_COMMIT(sb + (buf ? SM_MB1 : SM_MB0));
            }
        }
    }
    mbar_wait_parity(sb + SM_MB0, ph0 & 1);
    mbar_wait_parity(sb + SM_MB1, ph1 & 1);
    TCGEN05_FENCE_AFTER();

    // Epilogue: TMEM -> SMEM (transpose-stage) -> coalesced GMEM, fused v0 colsums.
    float* smt = (float*)(smem + SM_A0);        // 128 rows x 36 floats (padded)
    float* colsum = (float*)(smem + SM_COLSUM); // 32 floats
    for (int cc = 0; cc < 8; cc++) {
        if (tid < 32) colsum[tid] = 0.f;
        __syncthreads();
        if (wid < 4) {
            uint32_t regs[32];
            LD32X32_X32(regs, tmem + cc * 32);
            TCGEN05_WAIT_LD();
            float* dst = smt + (wid * 32 + lane) * 36;
#pragma unroll
            for (int c = 0; c < 32; c++) dst[c] = __uint_as_float(regs[c]);
        }
        __syncthreads();
        int c = tid & 31, r0 = tid >> 5;
        float lsum = 0.f;
#pragma unroll
        for (int p = 0; p < 16; p++) {
            int r = r0 + p * 8;
            float v = smt[r * 36 + c];
            lsum += v;
            g_U[(size_t)(rowBase + r) * NOF + colBase + cc * 32 + c] = v;
        }
        atomicAdd(&colsum[c], lsum);
        __syncthreads();
        if (tid < 32)
            atomicAdd(&g_vacc[b * NOF + colBase + cc * 32 + tid], colsum[tid] * (1.0f / 32.0f));
    }

    __syncthreads();
    if (tid == 0) { MBAR_INVAL(sb + SM_MB0); MBAR_INVAL(sb + SM_MB1); }
    __syncthreads();
    if (wid == 0) TCGEN05_DEALLOC(tmem, 256);

#else  // ---------- FFMA2 fallback (plain sm_103 pass; same outputs) ----------
    float* As = (float*)(smem);                 // [8][128]
    float* Bs = (float*)(smem + 4096);          // [8][128]
    float* colsum = (float*)(smem + 8192);      // [128]
    const int K = NH, N = NOF;
    int tr = tid >> 4, tc = tid & 15;

    for (int half = 0; half < 2; half++) {
        int colBase2 = colBase + half * 128;
        const float* Ag = X + (size_t)(rowBase + (tid >> 1)) * K + ((tid & 1) << 2);
        const float* Bg = W + (size_t)(tid >> 5) * N + colBase2 + ((tid & 31) << 2);

        unsigned long long acc[8][4];
#pragma unroll
        for (int i = 0; i < 8; i++)
#pragma unroll
            for (int j = 0; j < 4; j++) acc[i][j] = 0ull;

        if (tid < 128) colsum[tid] = 0.f;
        __syncthreads();

        for (int kt = 0; kt < K; kt += 8) {
            float4 a = *(const float4*)(Ag + kt);
            int ac = (tid & 1) << 2, ar = tid >> 1;
            As[(ac + 0) * 128 + ar] = a.x;
            As[(ac + 1) * 128 + ar] = a.y;
            As[(ac + 2) * 128 + ar] = a.z;
            As[(ac + 3) * 128 + ar] = a.w;
            *(float4*)&Bs[(tid >> 5) * 128 + ((tid & 31) << 2)] =
                *(const float4*)(Bg + (size_t)kt * N);
            __syncthreads();
#pragma unroll
            for (int k = 0; k < 8; k++) {
                const ulonglong2* bp = (const ulonglong2*)&Bs[k * 128 + (tc << 3)];
                ulonglong2 b01 = bp[0], b23 = bp[1];
                const float* ap = &As[k * 128 + (tr << 3)];
#pragma unroll
                for (int i = 0; i < 8; i++) {
                    unsigned long long m2 = pack_dup(ap[i]);
                    ffma2(acc[i][0], m2, b01.x);
                    ffma2(acc[i][1], m2, b01.y);
                    ffma2(acc[i][2], m2, b23.x);
                    ffma2(acc[i][3], m2, b23.y);
                }
            }
            __syncthreads();
        }

        float cs[8];
#pragma unroll
        for (int j = 0; j < 8; j++) cs[j] = 0.f;
        float* Cg = g_U + (size_t)(rowBase + (tr << 3)) * N + colBase2 + (tc << 3);
#pragma unroll
        for (int i = 0; i < 8; i++) {
            float2 c0 = unpack2(acc[i][0]);
            float2 c1 = unpack2(acc[i][1]);
            float2 c2 = unpack2(acc[i][2]);
            float2 c3 = unpack2(acc[i][3]);
            *(float4*)(Cg + (size_t)i * N)     = make_float4(c0.x, c0.y, c1.x, c1.y);
            *(float4*)(Cg + (size_t)i * N + 4) = make_float4(c2.x, c2.y, c3.x, c3.y);
            cs[0] += c0.x; cs[1] += c0.y; cs[2] += c1.x; cs[3] += c1.y;
            cs[4] += c2.x; cs[5] += c2.y; cs[6] += c3.x; cs[7] += c3.y;
        }
#pragma unroll
        for (int j = 0; j < 8; j++) atomicAdd(&colsum[(tc << 3) + j], cs[j]);
        __syncthreads();
        if (tid < 128)
            atomicAdd(&g_vacc[b * NOF + colBase2 + tid], colsum[tid] * (1.0f / 32.0f));
        __syncthreads();
    }
#endif
}

// ---------------- Routing pass (iterations 2,3): fully coalesced ----------------
__global__ __launch_bounds__(256) void route_pass2() {
    __shared__ float vs[NOF];
    int b = blockIdx.x >> 3, chunk = blockIdx.x & 7;
    int warp = threadIdx.x >> 5, lane = threadIdx.x & 31;

    vs[threadIdx.x] = 0.f;
    vs[threadIdx.x + 256] = 0.f;

    float4 vr[4];
    const float4* vp = (const float4*)(g_vsq + b * NOF);
#pragma unroll
    for (int s = 0; s < 4; s++) vr[s] = vp[s * 32 + lane];
    __syncthreads();

    float4 acc[4];
#pragma unroll
    for (int s = 0; s < 4; s++) acc[s] = make_float4(0.f, 0.f, 0.f, 0.f);

    const float* Ub = g_U + (size_t)b * NI * NOF;
#pragma unroll
    for (int j = 0; j < 8; j++) {
        int i = (chunk << 6) + (warp << 3) + j;
        const float4* up = (const float4*)(Ub + (size_t)i * NOF);
        float4 u0 = up[lane], u1 = up[32 + lane], u2 = up[64 + lane], u3 = up[96 + lane];

        float b0 = u0.x * vr[0].x + u0.y * vr[0].y + u0.z * vr[0].z + u0.w * vr[0].w;
        float b1 = u1.x * vr[1].x + u1.y * vr[1].y + u1.z * vr[1].z + u1.w * vr[1].w;
        float b2 = u2.x * vr[2].x + u2.y * vr[2].y + u2.z * vr[2].z + u2.w * vr[2].w;
        float b3 = u3.x * vr[3].x + u3.y * vr[3].y + u3.z * vr[3].z + u3.w * vr[3].w;
        b0 += __shfl_xor_sync(~0u, b0, 1); b0 += __shfl_xor_sync(~0u, b0, 2);
        b1 += __shfl_xor_sync(~0u, b1, 1); b1 += __shfl_xor_sync(~0u, b1, 2);
        b2 += __shfl_xor_sync(~0u, b2, 1); b2 += __shfl_xor_sync(~0u, b2, 2);
        b3 += __shfl_xor_sync(~0u, b3, 1); b3 += __shfl_xor_sync(~0u, b3, 2);
        float mx = fmaxf(fmaxf(b0, b1), fmaxf(b2, b3));
        mx = fmaxf(mx, __shfl_xor_sync(~0u, mx, 4));
        mx = fmaxf(mx, __shfl_xor_sync(~0u, mx, 8));
        mx = fmaxf(mx, __shfl_xor_sync(~0u, mx, 16));
        float e0 = __expf(b0 - mx), e1 = __expf(b1 - mx);
        float e2 = __expf(b2 - mx), e3 = __expf(b3 - mx);
        float sum = e0 + e1 + e2 + e3;
        sum += __shfl_xor_sync(~0u, sum, 4);
        sum += __shfl_xor_sync(~0u, sum, 8);
        sum += __shfl_xor_sync(~0u, sum, 16);
        float inv = 1.0f / sum;
        float c0 = e0 * inv, c1 = e1 * inv, c2 = e2 * inv, c3 = e3 * inv;
        acc[0].x += c0 * u0.x; acc[0].y += c0 * u0.y; acc[0].z += c0 * u0.z; acc[0].w += c0 * u0.w;
        acc[1].x += c1 * u1.x; acc[1].y += c1 * u1.y; acc[1].z += c1 * u1.z; acc[1].w += c1 * u1.w;
        acc[2].x += c2 * u2.x; acc[2].y += c2 * u2.y; acc[2].z += c2 * u2.z; acc[2].w += c2 * u2.w;
        acc[3].x += c3 * u3.x; acc[3].y += c3 * u3.y; acc[3].z += c3 * u3.z; acc[3].w += c3 * u3.w;
    }

#pragma unroll
    for (int s = 0; s < 4; s++) {
        int base = (s * 8 + (lane >> 2)) * 16 + (lane & 3) * 4;
        atomicAdd(&vs[base + 0], acc[s].x);
        atomicAdd(&vs[base + 1], acc[s].y);
        atomicAdd(&vs[base + 2], acc[s].z);
        atomicAdd(&vs[base + 3], acc[s].w);
    }
    __syncthreads();
    atomicAdd(&g_vacc[b * NOF + threadIdx.x], vs[threadIdx.x]);
    atomicAdd(&g_vacc[b * NOF + 256 + threadIdx.x], vs[threadIdx.x + 256]);
}

// ---------------- Squash (also re-zeros g_vacc for replay-invariance) ----------------
__global__ __launch_bounds__(512) void squash_kernel(float* __restrict__ outp) {
    int idx = blockIdx.x * NOF + threadIdx.x;
    float val = g_vacc[idx];
    g_vacc[idx] = 0.f;
    float n2 = val * val;
#pragma unroll
    for (int m = 8; m > 0; m >>= 1)
        n2 += __shfl_xor_sync(~0u, n2, m);   // sum over the 16 f-lanes
    float scale = sqrtf(n2) / (1.0f + n2);
    float r = val * scale;
    if (outp) outp[idx] = r;
    else g_vsq[idx] = r;
}

extern "C" void kernel_launch(void* const* d_in, const int* in_sizes, int n_in,
                              void* d_out, int out_size) {
    const float* x = (const float*)d_in[0];   // [128, 512, 256]
    const float* W = (const float*)d_in[1];   // [1, 256, 512]
    float* out = (float*)d_out;               // [128, 32, 16]

    cudaFuncSetAttribute(gemm_tc, cudaFuncAttributeMaxDynamicSharedMemorySize, GEMM_SMEM);

    wt_kernel<<<512, 256>>>(W);
    gemm_tc<<<dim3(2, 512), 256, GEMM_SMEM>>>(x, W);   // U + fused iter-1 accumulation
    squash_kernel<<<NB, 512>>>(nullptr);               // v1
    route_pass2<<<NB * 8, 256>>>();                    // iter 2
    squash_kernel<<<NB, 512>>>(nullptr);               // v2
    route_pass2<<<NB * 8, 256>>>();                    // iter 3
    squash_kernel<<<NB, 512>>>(out);                   // v3 -> output
}

// round 4
// speedup vs baseline: 3.7367x; 1.2748x over previous
#include <cuda_runtime.h>
#include <cstdint>

#define NB 128
#define NI 512
#define NH 256
#define NOF 512   // O*F = 32*16

// Arch-feature gate: tcgen05 only exists in the sm_103a (arch-specific) pass.
#if defined(__CUDA_ARCH__) && \
    (defined(__CUDA_ARCH_FEAT_SM103_ALL) || defined(__CUDA_ARCH_FEAT_SM101_ALL) || \
     (defined(__CUDA_ARCH_SPECIFIC__) && (__CUDA_ARCH_SPECIFIC__ == 1030)))
#define TC_PATH 1
#else
#define TC_PATH 0
#endif

// ---------------- device scratch (allocation-free rule) ----------------
__device__ float g_U[(size_t)NB * NI * NOF];   // u: [B*I, 512] row-major
__device__ float g_Wt[NOF * NH];               // W^T [512, 256], tf32-rounded
__device__ float g_vacc[NB * NOF];
__device__ float g_vsq[NB * NOF];

// ---------------- generic helpers ----------------
__device__ __forceinline__ uint32_t smem_u32(const void* p) {
    uint32_t a;
    asm("{ .reg .u64 t; cvta.to.shared.u64 t, %1; cvt.u32.u64 %0, t; }" : "=r"(a) : "l"(p));
    return a;
}
__device__ __forceinline__ float to_tf32(float x) {
    float r;
    asm("cvt.rna.tf32.f32 %0, %1;" : "=f"(r) : "f"(x));
    return r;
}
__device__ __forceinline__ uint32_t sw128(uint32_t off) { return off ^ ((off >> 3) & 0x70); }

// packed f32x2 helpers (fallback GEMM)
__device__ __forceinline__ unsigned long long pack_dup(float a) {
    unsigned long long r;
    asm("mov.b64 %0, {%1, %1};" : "=l"(r) : "f"(a));
    return r;
}
__device__ __forceinline__ void ffma2(unsigned long long& d, unsigned long long a,
                                      unsigned long long b) {
    asm("fma.rn.f32x2 %0, %1, %2, %0;" : "+l"(d) : "l"(a), "l"(b));
}
__device__ __forceinline__ float2 unpack2(unsigned long long v) {
    float2 f;
    asm("mov.b64 {%0, %1}, %2;" : "=f"(f.x), "=f"(f.y) : "l"(v));
    return f;
}

// ---------------- W transpose (coalesced, tiled) : g_Wt[n][k] = tf32(W[k][n]) -------
// W: [256, 512]. grid (16, 8) tiles of 32x32, block (32, 8).
__global__ void wt_kernel(const float* __restrict__ W) {
    __shared__ float tile[32][33];
    int x = blockIdx.x * 32 + threadIdx.x;   // n
    int y = blockIdx.y * 32 + threadIdx.y;   // k
#pragma unroll
    for (int j = 0; j < 32; j += 8)
        tile[threadIdx.y + j][threadIdx.x] = W[(size_t)(y + j) * NOF + x];
    __syncthreads();
    int xo = blockIdx.y * 32 + threadIdx.x;  // k
    int yo = blockIdx.x * 32 + threadIdx.y;  // n
#pragma unroll
    for (int j = 0; j < 32; j += 8)
        g_Wt[(size_t)(yo + j) * NH + xo] = to_tf32(tile[threadIdx.x][threadIdx.y + j]);
}

// ---------------- SMEM layout for the GEMM kernel ----------------
#define SM_TMEM 0
#define SM_MB0 8
#define SM_MB1 16
#define SM_COLSUM 512
#define SM_A0 1024
#define SM_A1 (SM_A0 + 16384)
#define SM_B0 (SM_A1 + 16384)
#define SM_B1 (SM_B0 + 32768)
#define GEMM_SMEM (SM_B1 + 32768 + 128)

#if TC_PATH
// ---------------- tcgen05-only PTX helpers ----------------
__device__ __forceinline__ uint32_t elect_one_pred() {
    uint32_t pred;
    asm volatile("{\n\t.reg .pred p;\n\telect.sync _|p, 0xFFFFFFFF;\n\t"
                 "selp.b32 %0, 1, 0, p;\n\t}" : "=r"(pred));
    return pred;
}
#define TCGEN05_ALLOC(sa, n) \
    asm volatile("tcgen05.alloc.cta_group::1.sync.aligned.shared::cta.b32 [%0], %1;" \
                 :: "r"((uint32_t)(sa)), "r"((uint32_t)(n)) : "memory")
#define TCGEN05_DEALLOC(t, n) \
    asm volatile("tcgen05.dealloc.cta_group::1.sync.aligned.b32 %0, %1;" :: "r"(t), "r"((uint32_t)(n)))
#define TCGEN05_RELINQ() \
    asm volatile("tcgen05.relinquish_alloc_permit.cta_group::1.sync.aligned;")
#define TCGEN05_COMMIT(mb) \
    asm volatile("tcgen05.commit.cta_group::1.mbarrier::arrive::one.shared::cluster.b64 [%0];" \
                 :: "r"((uint32_t)(mb)) : "memory")
#define TCGEN05_FENCE_AFTER() asm volatile("tcgen05.fence::after_thread_sync;" ::: "memory")
#define TCGEN05_WAIT_LD() asm volatile("tcgen05.wait::ld.sync.aligned;" ::: "memory")
#define FENCE_ASYNC_SHARED() asm volatile("fence.proxy.async.shared::cta;" ::: "memory")
#define MBAR_INIT(mb, c) \
    asm volatile("mbarrier.init.shared.b64 [%0], %1;" :: "r"((uint32_t)(mb)), "r"((uint32_t)(c)) : "memory")
#define MBAR_INVAL(mb) \
    asm volatile("mbarrier.inval.shared.b64 [%0];" :: "r"((uint32_t)(mb)) : "memory")

__device__ __forceinline__ void mbar_wait_parity(uint32_t mb, uint32_t parity) {
    asm volatile(
        "{\n\t.reg .pred P1;\n\t"
        "WAIT_LOOP_%=:\n\t"
        "mbarrier.try_wait.parity.acquire.cta.shared::cta.b64 P1, [%0], %1, 0x989680;\n\t"
        "@P1 bra.uni WAIT_DONE_%=;\n\t"
        "bra.uni WAIT_LOOP_%=;\n\t"
        "WAIT_DONE_%=:\n\t}"
        :: "r"(mb), "r"(parity) : "memory");
}

#define LD32X32_X32(r, ta) \
    asm volatile( \
        "tcgen05.ld.sync.aligned.32x32b.x32.b32 " \
        "{%0, %1, %2, %3, %4, %5, %6, %7, %8, %9, %10, %11, %12, %13, %14, %15, " \
        " %16, %17, %18, %19, %20, %21, %22, %23, %24, %25, %26, %27, %28, %29, %30, %31}, [%32];" \
        : "=r"((r)[0]),  "=r"((r)[1]),  "=r"((r)[2]),  "=r"((r)[3]), \
          "=r"((r)[4]),  "=r"((r)[5]),  "=r"((r)[6]),  "=r"((r)[7]), \
          "=r"((r)[8]),  "=r"((r)[9]),  "=r"((r)[10]), "=r"((r)[11]), \
          "=r"((r)[12]), "=r"((r)[13]), "=r"((r)[14]), "=r"((r)[15]), \
          "=r"((r)[16]), "=r"((r)[17]), "=r"((r)[18]), "=r"((r)[19]), \
          "=r"((r)[20]), "=r"((r)[21]), "=r"((r)[22]), "=r"((r)[23]), \
          "=r"((r)[24]), "=r"((r)[25]), "=r"((r)[26]), "=r"((r)[27]), \
          "=r"((r)[28]), "=r"((r)[29]), "=r"((r)[30]), "=r"((r)[31]) \
        : "r"(ta))

__device__ __forceinline__ void mma_tf32_ss(uint32_t d, uint64_t ad, uint64_t bd,
                                            uint32_t idesc, bool en) {
    uint32_t e = en ? 1u : 0u, z = 0u;
    asm volatile(
        "{\n\t.reg .pred p;\n\tsetp.ne.u32 p, %6, 0;\n\t"
        "tcgen05.mma.cta_group::1.kind::tf32 [%0], %1, %2, %3, {%4, %4, %4, %4}, p;\n\t}"
        :: "r"(d), "l"(ad), "l"(bd), "r"(idesc), "r"(z), "r"(z), "r"(e)
        : "memory");
}
__device__ __forceinline__ uint64_t make_desc_sw128(uint32_t base) {
    const uint64_t BASE =
        (uint64_t(2) << 61) | (uint64_t(1) << 46) | (uint64_t(64) << 32) | (uint64_t(1) << 16);
    return BASE | ((uint64_t)(base >> 4) & 0x3FFF);
}
#define TF32_IDESC (0x10u | (2u << 7) | (2u << 10) | ((256u >> 3) << 17) | ((128u >> 4) << 24))

__device__ __forceinline__ void cp_async16(uint32_t dst, const void* src) {
    asm volatile("cp.async.cg.shared.global [%0], [%1], 16;" :: "r"(dst), "l"(src));
}
#define CP_COMMIT() asm volatile("cp.async.commit_group;" ::: "memory")
#define CP_WAIT0()  asm volatile("cp.async.wait_group 0;" ::: "memory")
#endif  // TC_PATH

// ---------------- GEMM: U[65536, 512] = X[65536, 256] * W, fused iter-1 colsums ------
// grid = (2, 512), 256 threads. Per CTA: 128 rows x 256 cols.
// Pipelined: B tiles via cp.async (2-stage), A tiles via register prefetch + cvt.
__global__ __launch_bounds__(256) void gemm_tc(const float* __restrict__ X,
                                               const float* __restrict__ W) {
    extern __shared__ char smem[];
    int tid = threadIdx.x;
    int rowBase = blockIdx.y << 7;
    int colBase = blockIdx.x << 8;
    int b = rowBase >> 9;                // batch index (512 rows per batch)

#if TC_PATH
    const uint32_t sb = smem_u32(smem);
    int wid = tid >> 5, lane = tid & 31;

    if (wid == 0) {
        TCGEN05_ALLOC(sb + SM_TMEM, 256);
        TCGEN05_RELINQ();
    }
    if (tid == 0) { MBAR_INIT(sb + SM_MB0, 1); MBAR_INIT(sb + SM_MB1, 1); }
    __syncthreads();
    uint32_t tmem;
    asm volatile("ld.shared.b32 %0, [%1];" : "=r"(tmem) : "r"(sb + SM_TMEM));

    // Per-thread load coordinates (A: 4 units, B: 8 units)
    int ar_[4], aj_[4], br_[8], bj_[8];
#pragma unroll
    for (int p = 0; p < 4; p++) { int u = tid + (p << 8); ar_[p] = u >> 3; aj_[p] = u & 7; }
#pragma unroll
    for (int p = 0; p < 8; p++) { int u = tid + (p << 8); br_[p] = u >> 3; bj_[p] = u & 7; }

    // Prologue: A(0) into regs, B(0) via cp.async
    float4 ra[4];
#pragma unroll
    for (int p = 0; p < 4; p++)
        ra[p] = *(const float4*)(X + (size_t)(rowBase + ar_[p]) * NH + aj_[p] * 4);
#pragma unroll
    for (int p = 0; p < 8; p++)
        cp_async16(sb + SM_B0 + sw128(br_[p] * 128 + bj_[p] * 16),
                   g_Wt + (size_t)(colBase + br_[p]) * NH + bj_[p] * 4);
    CP_COMMIT();

    int ph0 = 0, ph1 = 0;
    for (int ch = 0; ch < 8; ch++) {
        int buf = ch & 1;
        uint32_t Aoff = buf ? SM_A1 : SM_A0;
        uint32_t Boff = buf ? SM_B1 : SM_B0;

        // A regs -> SMEM (tf32 convert + swizzle). Buffer freed by wait done at prep.
#pragma unroll
        for (int p = 0; p < 4; p++) {
            float4 v = ra[p];
            v.x = to_tf32(v.x); v.y = to_tf32(v.y); v.z = to_tf32(v.z); v.w = to_tf32(v.w);
            *(float4*)(smem + Aoff + sw128(ar_[p] * 128 + aj_[p] * 16)) = v;
        }
        CP_WAIT0();                 // B(ch) arrived
        FENCE_ASYNC_SHARED();
        __syncthreads();

        if (wid == 0) {
            uint64_t ad = make_desc_sw128(sb + Aoff);
            uint64_t bd = make_desc_sw128(sb + Boff);
            if (elect_one_pred()) {
#pragma unroll
                for (int k = 0; k < 4; k++)
                    mma_tf32_ss(tmem, ad + k * 2, bd + k * 2, TF32_IDESC, (ch > 0) || (k > 0));
                TCGEN05_COMMIT(sb + (buf ? SM_MB1 : SM_MB0));
            }
        }

        // Prep chunk ch+1: wait MMA(ch-1) (frees nbuf), then issue loads overlapping MMA(ch)
        if (ch < 7) {
            int nb = (ch + 1) & 1;
            if (ch >= 1) {
                if (nb == 0) { mbar_wait_parity(sb + SM_MB0, ph0 & 1); ph0++; }
                else         { mbar_wait_parity(sb + SM_MB1, ph1 & 1); ph1++; }
            }
            int kk = (ch + 1) * 32;
            uint32_t nBoff = nb ? SM_B1 : SM_B0;
#pragma unroll
            for (int p = 0; p < 4; p++)
                ra[p] = *(const float4*)(X + (size_t)(rowBase + ar_[p]) * NH + kk + aj_[p] * 4);
#pragma unroll
            for (int p = 0; p < 8; p++)
                cp_async16(sb + nBoff + sw128(br_[p] * 128 + bj_[p] * 16),
                           g_Wt + (size_t)(colBase + br_[p]) * NH + kk + bj_[p] * 4);
            CP_COMMIT();
        }
    }
    mbar_wait_parity(sb + SM_MB0, ph0 & 1);   // final MMA on buf0 (ch=6)
    mbar_wait_parity(sb + SM_MB1, ph1 & 1);   // final MMA on buf1 (ch=7)
    TCGEN05_FENCE_AFTER();

    // Epilogue: TMEM -> SMEM (transpose-stage) -> coalesced GMEM, fused v0 colsums.
    float* smt = (float*)(smem + SM_A0);        // 128 rows x 36 floats (padded)
    float* colsum = (float*)(smem + SM_COLSUM); // 32 floats
    for (int cc = 0; cc < 8; cc++) {
        if (tid < 32) colsum[tid] = 0.f;
        __syncthreads();
        if (wid < 4) {
            uint32_t regs[32];
            LD32X32_X32(regs, tmem + cc * 32);
            TCGEN05_WAIT_LD();
            float* dst = smt + (wid * 32 + lane) * 36;
#pragma unroll
            for (int c = 0; c < 32; c++) dst[c] = __uint_as_float(regs[c]);
        }
        __syncthreads();
        int c = tid & 31, r0 = tid >> 5;
        float lsum = 0.f;
#pragma unroll
        for (int p = 0; p < 16; p++) {
            int r = r0 + p * 8;
            float v = smt[r * 36 + c];
            lsum += v;
            g_U[(size_t)(rowBase + r) * NOF + colBase + cc * 32 + c] = v;
        }
        atomicAdd(&colsum[c], lsum);
        __syncthreads();
        if (tid < 32)
            atomicAdd(&g_vacc[b * NOF + colBase + cc * 32 + tid], colsum[tid] * (1.0f / 32.0f));
    }

    __syncthreads();
    if (tid == 0) { MBAR_INVAL(sb + SM_MB0); MBAR_INVAL(sb + SM_MB1); }
    __syncthreads();
    if (wid == 0) TCGEN05_DEALLOC(tmem, 256);

#else  // ---------- FFMA2 fallback (plain sm_103 pass; same outputs) ----------
    float* As = (float*)(smem);                 // [8][128]
    float* Bs = (float*)(smem + 4096);          // [8][128]
    float* colsum = (float*)(smem + 8192);      // [128]
    const int K = NH, N = NOF;
    int tr = tid >> 4, tc = tid & 15;

    for (int half = 0; half < 2; half++) {
        int colBase2 = colBase + half * 128;
        const float* Ag = X + (size_t)(rowBase + (tid >> 1)) * K + ((tid & 1) << 2);
        const float* Bg = W + (size_t)(tid >> 5) * N + colBase2 + ((tid & 31) << 2);

        unsigned long long acc[8][4];
#pragma unroll
        for (int i = 0; i < 8; i++)
#pragma unroll
            for (int j = 0; j < 4; j++) acc[i][j] = 0ull;

        if (tid < 128) colsum[tid] = 0.f;
        __syncthreads();

        for (int kt = 0; kt < K; kt += 8) {
            float4 a = *(const float4*)(Ag + kt);
            int ac = (tid & 1) << 2, ar = tid >> 1;
            As[(ac + 0) * 128 + ar] = a.x;
            As[(ac + 1) * 128 + ar] = a.y;
            As[(ac + 2) * 128 + ar] = a.z;
            As[(ac + 3) * 128 + ar] = a.w;
            *(float4*)&Bs[(tid >> 5) * 128 + ((tid & 31) << 2)] =
                *(const float4*)(Bg + (size_t)kt * N);
            __syncthreads();
#pragma unroll
            for (int k = 0; k < 8; k++) {
                const ulonglong2* bp = (const ulonglong2*)&Bs[k * 128 + (tc << 3)];
                ulonglong2 b01 = bp[0], b23 = bp[1];
                const float* ap = &As[k * 128 + (tr << 3)];
#pragma unroll
                for (int i = 0; i < 8; i++) {
                    unsigned long long m2 = pack_dup(ap[i]);
                    ffma2(acc[i][0], m2, b01.x);
                    ffma2(acc[i][1], m2, b01.y);
                    ffma2(acc[i][2], m2, b23.x);
                    ffma2(acc[i][3], m2, b23.y);
                }
            }
            __syncthreads();
        }

        float cs[8];
#pragma unroll
        for (int j = 0; j < 8; j++) cs[j] = 0.f;
        float* Cg = g_U + (size_t)(rowBase + (tr << 3)) * N + colBase2 + (tc << 3);
#pragma unroll
        for (int i = 0; i < 8; i++) {
            float2 c0 = unpack2(acc[i][0]);
            float2 c1 = unpack2(acc[i][1]);
            float2 c2 = unpack2(acc[i][2]);
            float2 c3 = unpack2(acc[i][3]);
            *(float4*)(Cg + (size_t)i * N)     = make_float4(c0.x, c0.y, c1.x, c1.y);
            *(float4*)(Cg + (size_t)i * N + 4) = make_float4(c2.x, c2.y, c3.x, c3.y);
            cs[0] += c0.x; cs[1] += c0.y; cs[2] += c1.x; cs[3] += c1.y;
            cs[4] += c2.x; cs[5] += c2.y; cs[6] += c3.x; cs[7] += c3.y;
        }
#pragma unroll
        for (int j = 0; j < 8; j++) atomicAdd(&colsum[(tc << 3) + j], cs[j]);
        __syncthreads();
        if (tid < 128)
            atomicAdd(&g_vacc[b * NOF + colBase2 + tid], colsum[tid] * (1.0f / 32.0f));
        __syncthreads();
    }
#endif
}

// ---------------- Routing pass (iterations 2,3): coalesced, 2-row ILP ----------------
// grid = NB*4 (block = 128 rows), 256 threads; warp handles 16 rows, 2 in flight.
__global__ __launch_bounds__(256) void route_pass2() {
    __shared__ float vs[NOF];
    int b = blockIdx.x >> 2, chunk = blockIdx.x & 3;
    int warp = threadIdx.x >> 5, lane = threadIdx.x & 31;

    vs[threadIdx.x] = 0.f;
    vs[threadIdx.x + 256] = 0.f;

    float4 vr[4];
    const float4* vp = (const float4*)(g_vsq + b * NOF);
#pragma unroll
    for (int s = 0; s < 4; s++) vr[s] = vp[s * 32 + lane];
    __syncthreads();

    float4 acc[4];
#pragma unroll
    for (int s = 0; s < 4; s++) acc[s] = make_float4(0.f, 0.f, 0.f, 0.f);

    const float* Ub = g_U + (size_t)b * NI * NOF;
    for (int jj = 0; jj < 16; jj += 2) {
        int i0 = (chunk << 7) + (warp << 4) + jj;
        const float4* up = (const float4*)(Ub + (size_t)i0 * NOF);
        // row 0 and row 1 loads batched (8 LDG.128 in flight)
        float4 u0 = up[lane], u1 = up[32 + lane], u2 = up[64 + lane], u3 = up[96 + lane];
        float4 w0 = up[128 + lane], w1 = up[160 + lane], w2 = up[192 + lane], w3 = up[224 + lane];

        float a0 = u0.x * vr[0].x + u0.y * vr[0].y + u0.z * vr[0].z + u0.w * vr[0].w;
        float a1 = u1.x * vr[1].x + u1.y * vr[1].y + u1.z * vr[1].z + u1.w * vr[1].w;
        float a2 = u2.x * vr[2].x + u2.y * vr[2].y + u2.z * vr[2].z + u2.w * vr[2].w;
        float a3 = u3.x * vr[3].x + u3.y * vr[3].y + u3.z * vr[3].z + u3.w * vr[3].w;
        float d0 = w0.x * vr[0].x + w0.y * vr[0].y + w0.z * vr[0].z + w0.w * vr[0].w;
        float d1 = w1.x * vr[1].x + w1.y * vr[1].y + w1.z * vr[1].z + w1.w * vr[1].w;
        float d2 = w2.x * vr[2].x + w2.y * vr[2].y + w2.z * vr[2].z + w2.w * vr[2].w;
        float d3 = w3.x * vr[3].x + w3.y * vr[3].y + w3.z * vr[3].z + w3.w * vr[3].w;

        a0 += __shfl_xor_sync(~0u, a0, 1); d0 += __shfl_xor_sync(~0u, d0, 1);
        a1 += __shfl_xor_sync(~0u, a1, 1); d1 += __shfl_xor_sync(~0u, d1, 1);
        a2 += __shfl_xor_sync(~0u, a2, 1); d2 += __shfl_xor_sync(~0u, d2, 1);
        a3 += __shfl_xor_sync(~0u, a3, 1); d3 += __shfl_xor_sync(~0u, d3, 1);
        a0 += __shfl_xor_sync(~0u, a0, 2); d0 += __shfl_xor_sync(~0u, d0, 2);
        a1 += __shfl_xor_sync(~0u, a1, 2); d1 += __shfl_xor_sync(~0u, d1, 2);
        a2 += __shfl_xor_sync(~0u, a2, 2); d2 += __shfl_xor_sync(~0u, d2, 2);
        a3 += __shfl_xor_sync(~0u, a3, 2); d3 += __shfl_xor_sync(~0u, d3, 2);

        float mxa = fmaxf(fmaxf(a0, a1), fmaxf(a2, a3));
        float mxd = fmaxf(fmaxf(d0, d1), fmaxf(d2, d3));
        mxa = fmaxf(mxa, __shfl_xor_sync(~0u, mxa, 4));
        mxd = fmaxf(mxd, __shfl_xor_sync(~0u, mxd, 4));
        mxa = fmaxf(mxa, __shfl_xor_sync(~0u, mxa, 8));
        mxd = fmaxf(mxd, __shfl_xor_sync(~0u, mxd, 8));
        mxa = fmaxf(mxa, __shfl_xor_sync(~0u, mxa, 16));
        mxd = fmaxf(mxd, __shfl_xor_sync(~0u, mxd, 16));

        float ea0 = __expf(a0 - mxa), ea1 = __expf(a1 - mxa);
        float ea2 = __expf(a2 - mxa), ea3 = __expf(a3 - mxa);
        float ed0 = __expf(d0 - mxd), ed1 = __expf(d1 - mxd);
        float ed2 = __expf(d2 - mxd), ed3 = __expf(d3 - mxd);
        float sa = ea0 + ea1 + ea2 + ea3;
        float sd = ed0 + ed1 + ed2 + ed3;
        sa += __shfl_xor_sync(~0u, sa, 4);  sd += __shfl_xor_sync(~0u, sd, 4);
        sa += __shfl_xor_sync(~0u, sa, 8);  sd += __shfl_xor_sync(~0u, sd, 8);
        sa += __shfl_xor_sync(~0u, sa, 16); sd += __shfl_xor_sync(~0u, sd, 16);
        float ia = 1.0f / sa, id = 1.0f / sd;
        float c0 = ea0 * ia, c1 = ea1 * ia, c2 = ea2 * ia, c3 = ea3 * ia;
        float e0 = ed0 * id, e1 = ed1 * id, e2 = ed2 * id, e3 = ed3 * id;

        acc[0].x += c0 * u0.x + e0 * w0.x; acc[0].y += c0 * u0.y + e0 * w0.y;
        acc[0].z += c0 * u0.z + e0 * w0.z; acc[0].w += c0 * u0.w + e0 * w0.w;
        acc[1].x += c1 * u1.x + e1 * w1.x; acc[1].y += c1 * u1.y + e1 * w1.y;
        acc[1].z += c1 * u1.z + e1 * w1.z; acc[1].w += c1 * u1.w + e1 * w1.w;
        acc[2].x += c2 * u2.x + e2 * w2.x; acc[2].y += c2 * u2.y + e2 * w2.y;
        acc[2].z += c2 * u2.z + e2 * w2.z; acc[2].w += c2 * u2.w + e2 * w2.w;
        acc[3].x += c3 * u3.x + e3 * w3.x; acc[3].y += c3 * u3.y + e3 * w3.y;
        acc[3].z += c3 * u3.z + e3 * w3.z; acc[3].w += c3 * u3.w + e3 * w3.w;
    }

#pragma unroll
    for (int s = 0; s < 4; s++) {
        int base = (s * 8 + (lane >> 2)) * 16 + (lane & 3) * 4;
        atomicAdd(&vs[base + 0], acc[s].x);
        atomicAdd(&vs[base + 1], acc[s].y);
        atomicAdd(&vs[base + 2], acc[s].z);
        atomicAdd(&vs[base + 3], acc[s].w);
    }
    __syncthreads();
    atomicAdd(&g_vacc[b * NOF + threadIdx.x], vs[threadIdx.x]);
    atomicAdd(&g_vacc[b * NOF + 256 + threadIdx.x], vs[threadIdx.x + 256]);
}

// ---------------- Squash (also re-zeros g_vacc for replay-invariance) ----------------
__global__ __launch_bounds__(512) void squash_kernel(float* __restrict__ outp) {
    int idx = blockIdx.x * NOF + threadIdx.x;
    float val = g_vacc[idx];
    g_vacc[idx] = 0.f;
    float n2 = val * val;
#pragma unroll
    for (int m = 8; m > 0; m >>= 1)
        n2 += __shfl_xor_sync(~0u, n2, m);   // sum over the 16 f-lanes
    float scale = sqrtf(n2) / (1.0f + n2);
    float r = val * scale;
    if (outp) outp[idx] = r;
    else g_vsq[idx] = r;
}

extern "C" void kernel_launch(void* const* d_in, const int* in_sizes, int n_in,
                              void* d_out, int out_size) {
    const float* x = (const float*)d_in[0];   // [128, 512, 256]
    const float* W = (const float*)d_in[1];   // [1, 256, 512]
    float* out = (float*)d_out;               // [128, 32, 16]

    cudaFuncSetAttribute(gemm_tc, cudaFuncAttributeMaxDynamicSharedMemorySize, GEMM_SMEM);

    wt_kernel<<<dim3(16, 8), dim3(32, 8)>>>(W);
    gemm_tc<<<dim3(2, 512), 256, GEMM_SMEM>>>(x, W);   // U + fused iter-1 accumulation
    squash_kernel<<<NB, 512>>>(nullptr);               // v1
    route_pass2<<<NB * 4, 256>>>();                    // iter 2
    squash_kernel<<<NB, 512>>>(nullptr);               // v2
    route_pass2<<<NB * 4, 256>>>();                    // iter 3
    squash_kernel<<<NB, 512>>>(out);                   // v3 -> output
}